// round 9
// baseline (speedup 1.0000x reference)
#include <cuda_runtime.h>
#include <cuda_bf16.h>
#include <cstdint>
#include <math.h>

#define TS 4096
#define CM 1024
#define NH 16
#define DFF 4096

typedef unsigned short u16;

// ----------------------------- scratch (no allocs) -----------------------------
__device__ __align__(256) u16 g_h_hi[TS * CM];
__device__ __align__(256) u16 g_h_lo[TS * CM];
__device__ __align__(256) u16 g_qkv_hi[TS * 3 * CM];
__device__ __align__(256) u16 g_qkv_lo[TS * 3 * CM];
__device__ __align__(256) u16 g_vt_hi[NH * 64 * TS];
__device__ __align__(256) u16 g_vt_lo[NH * 64 * TS];
__device__ __align__(256) u16 g_ctx_hi[TS * CM];
__device__ __align__(256) u16 g_ctx_lo[TS * CM];
__device__ __align__(256) u16 g_ff1_hi[TS * DFF];
__device__ __align__(256) u16 g_ff1_lo[TS * DFF];
__device__ __align__(256) u16 g_wqkv_hi[3 * CM * CM];
__device__ __align__(256) u16 g_wqkv_lo[3 * CM * CM];
__device__ __align__(256) u16 g_wout_hi[CM * CM];
__device__ __align__(256) u16 g_wout_lo[CM * CM];
__device__ __align__(256) u16 g_w1_hi[DFF * CM];
__device__ __align__(256) u16 g_w1_lo[DFF * CM];
__device__ __align__(256) u16 g_w2_hi[CM * DFF];
__device__ __align__(256) u16 g_w2_lo[CM * DFF];
__device__ __align__(256) float g_x1[TS * CM];

// ----------------------------- helpers -----------------------------------------
__device__ __forceinline__ uint32_t smem_u32(const void* p) {
    uint32_t a;
    asm("{ .reg .u64 t; cvta.to.shared.u64 t, %1; cvt.u32.u64 %0, t; }" : "=r"(a) : "l"(p));
    return a;
}
__device__ __forceinline__ uint32_t sw128(uint32_t off) { return off ^ ((off >> 3) & 0x70); }
__device__ __forceinline__ float thi(float x) {
    return __uint_as_float(__float_as_uint(x) & 0xffff0000u);
}
__device__ __forceinline__ uint32_t cv2(float e0, float e1) {  // low half = bf16(e0)
    uint32_t r;
    asm("cvt.rn.bf16x2.f32 %0, %1, %2;" : "=r"(r) : "f"(e1), "f"(e0));
    return r;
}
__device__ __forceinline__ uint32_t hp2(float v0, float v1) {  // (trunc16(v0),trunc16(v1))
    return __byte_perm(__float_as_uint(v0), __float_as_uint(v1), 0x7632);
}
__device__ __forceinline__ uint32_t lp2(float v0, float v1) {
    return cv2(v0 - thi(v0), v1 - thi(v1));
}
__device__ __forceinline__ void conv8(float4 a, float4 b, uint4& hi, uint4& lo) {
    hi.x = hp2(a.x, a.y); hi.y = hp2(a.z, a.w);
    hi.z = hp2(b.x, b.y); hi.w = hp2(b.z, b.w);
    lo.x = lp2(a.x, a.y); lo.y = lp2(a.z, a.w);
    lo.z = lp2(b.x, b.y); lo.w = lp2(b.z, b.w);
}
__device__ __forceinline__ void cp16(uint32_t dst, const void* src) {
    asm volatile("cp.async.cg.shared.global [%0], [%1], 16;" :: "r"(dst), "l"(src));
}
__device__ __forceinline__ void cp_commit() {
    asm volatile("cp.async.commit_group;" ::: "memory");
}
template <int N>
__device__ __forceinline__ void cp_wait() {
    asm volatile("cp.async.wait_group %0;" :: "n"(N) : "memory");
}
__device__ __forceinline__ void ldsm4(uint32_t* r, uint32_t addr) {
    asm volatile("ldmatrix.sync.aligned.m8n8.x4.shared.b16 {%0,%1,%2,%3}, [%4];"
                 : "=r"(r[0]), "=r"(r[1]), "=r"(r[2]), "=r"(r[3]) : "r"(addr));
}
__device__ __forceinline__ void mma16816(float* c, const uint32_t* a, uint32_t b0, uint32_t b1) {
    asm volatile(
        "mma.sync.aligned.m16n8k16.row.col.f32.bf16.bf16.f32 "
        "{%0,%1,%2,%3}, {%4,%5,%6,%7}, {%8,%9}, {%0,%1,%2,%3};"
        : "+f"(c[0]), "+f"(c[1]), "+f"(c[2]), "+f"(c[3])
        : "r"(a[0]), "r"(a[1]), "r"(a[2]), "r"(a[3]), "r"(b0), "r"(b1));
}

// ------------------- warp-MMA GEMM on pre-split bf16 planes ---------------------
// C[M,N] = scale*(A @ B^T) + epi.  A: hi/lo planes [M,K] (or fp32 if CONVA),
// B: hi/lo planes [N,K].  BM=128, BK=64, 3-pass split accumulation.
// EPI: 0 none, 1 GELU, 2 +residual.  OSPLIT: write hi/lo bf16 planes instead of fp32.
template <int BN, int EPI, bool CSKIP, bool CKLIM, bool CONVA, bool OSPLIT>
__global__ __launch_bounds__(256, 1) void tgemm(
    const u16* __restrict__ Ahi, const u16* __restrict__ Alo,
    const float* __restrict__ Af, int lda, long long sAh,
    const u16* __restrict__ Bhi, const u16* __restrict__ Blo, int ldb, long long sBh,
    float* __restrict__ C, u16* __restrict__ Chi, u16* __restrict__ Clo,
    int ldc, long long sCh,
    const float* __restrict__ bias, const float* __restrict__ Res, int ldr,
    int K, float scale) {
    constexpr int SZAp = 128 * 128;          // one A plane: 128 rows x 128B
    constexpr int SZBp = BN * 128;
    constexpr int STAGE = 2 * SZAp + 2 * SZBp;
    constexpr int NBI = (BN * 8) / 256;      // 16B chunks per thread per B plane
    constexpr int WN = BN / 2;
    constexpr int NT8 = WN / 8;
    extern __shared__ char smem[];

    int m0 = blockIdx.y * 128;
    int n0 = blockIdx.x * BN;
    if (CSKIP && n0 >= m0 + 128) return;
    int h = blockIdx.z;
    if (CONVA) Af += (size_t)h * sAh;
    else { Ahi += (size_t)h * sAh; Alo += (size_t)h * sAh; }
    Bhi += (size_t)h * sBh;
    Blo += (size_t)h * sBh;
    // per-head output offset (THE R6 BUG: this was missing)
    if (OSPLIT) { Chi += (size_t)h * sCh; Clo += (size_t)h * sCh; }
    else        { C   += (size_t)h * sCh; }
    int kend = CKLIM ? ((m0 + 128 < K) ? (m0 + 128) : K) : K;
    int NC = kend >> 6;

    int tid = threadIdx.x;
    int lane = tid & 31, wid = tid >> 5;
    int wm = wid & 3, wn = wid >> 2;
    uint32_t sb = smem_u32(smem);

    float acc[2][NT8][4];
#pragma unroll
    for (int i = 0; i < 2; i++)
#pragma unroll
        for (int j = 0; j < NT8; j++)
#pragma unroll
            for (int q = 0; q < 4; q++) acc[i][j][q] = 0.f;

    int crow = tid >> 3, cchk = tid & 7;          // cp.async thread mapping

    float4 ra[4][2];                              // CONVA register staging

    auto cp_stageB = [&](int ci) {
        int b = ci & 1;
        uint32_t base = sb + b * STAGE + 2 * SZAp;
        int k0 = ci * 64;
#pragma unroll
        for (int i = 0; i < NBI; i++) {
            int row = crow + i * 32;
            uint32_t off = sw128(row * 128 + cchk * 16);
            const u16* s = Bhi + (size_t)(n0 + row) * ldb + k0 + cchk * 8;
            cp16(base + off, s);
        }
#pragma unroll
        for (int i = 0; i < NBI; i++) {
            int row = crow + i * 32;
            uint32_t off = sw128(row * 128 + cchk * 16);
            const u16* s = Blo + (size_t)(n0 + row) * ldb + k0 + cchk * 8;
            cp16(base + SZBp + off, s);
        }
    };
    auto cp_stageA = [&](int ci) {
        int b = ci & 1;
        uint32_t base = sb + b * STAGE;
        int k0 = ci * 64;
#pragma unroll
        for (int i = 0; i < 4; i++) {
            int row = crow + i * 32;
            uint32_t off = sw128(row * 128 + cchk * 16);
            cp16(base + off, Ahi + (size_t)(m0 + row) * lda + k0 + cchk * 8);
        }
#pragma unroll
        for (int i = 0; i < 4; i++) {
            int row = crow + i * 32;
            uint32_t off = sw128(row * 128 + cchk * 16);
            cp16(base + SZAp + off, Alo + (size_t)(m0 + row) * lda + k0 + cchk * 8);
        }
    };
    auto loadA_regs = [&](int ci) {
        int k0 = ci * 64;
#pragma unroll
        for (int i = 0; i < 4; i++) {
            int idx = tid + i * 256;
            int row = idx >> 3, g = idx & 7;
            const float* s = Af + (size_t)(m0 + row) * lda + k0 + g * 8;
            ra[i][0] = *(const float4*)s;
            ra[i][1] = *(const float4*)(s + 4);
        }
    };
    auto storeA = [&](int ci) {
        int b = ci & 1;
        char* bufp = smem + b * STAGE;
#pragma unroll
        for (int i = 0; i < 4; i++) {
            int idx = tid + i * 256;
            int row = idx >> 3, g = idx & 7;
            uint4 hi, lo;
            conv8(ra[i][0], ra[i][1], hi, lo);
            uint32_t off = sw128(row * 128 + g * 16);
            *(uint4*)(bufp + off) = hi;
            *(uint4*)(bufp + SZAp + off) = lo;
        }
    };
    auto mma_chunk = [&](int b) {
        uint32_t bA = sb + b * STAGE;
        uint32_t bB = bA + 2 * SZAp;
        int g = lane >> 3;
#pragma unroll
        for (int ks = 0; ks < 4; ks++) {
            int kb = ks * 32;
            uint32_t ahi[2][4], alo[2][4];
#pragma unroll
            for (int mt = 0; mt < 2; mt++) {
                int row = wm * 32 + mt * 16 + (g & 1) * 8 + (lane & 7);
                uint32_t off = sw128(row * 128 + kb + (g >> 1) * 16);
                ldsm4(ahi[mt], bA + off);
                ldsm4(alo[mt], bA + SZAp + off);
            }
#pragma unroll
            for (int nt2 = 0; nt2 < NT8 / 2; nt2++) {
                int row = wn * WN + nt2 * 16 + (g >> 1) * 8 + (lane & 7);
                uint32_t off = sw128(row * 128 + kb + (g & 1) * 16);
                uint32_t bhi[4], blo[4];
                ldsm4(bhi, bB + off);
                ldsm4(blo, bB + SZBp + off);
#pragma unroll
                for (int mt = 0; mt < 2; mt++) {
#pragma unroll
                    for (int j = 0; j < 2; j++) {
                        float* c = acc[mt][nt2 * 2 + j];
                        mma16816(c, ahi[mt], bhi[2 * j], bhi[2 * j + 1]);
                        mma16816(c, ahi[mt], blo[2 * j], blo[2 * j + 1]);
                        mma16816(c, alo[mt], bhi[2 * j], bhi[2 * j + 1]);
                    }
                }
            }
        }
    };

    // ---- prologue ----
    if (CONVA) {
        loadA_regs(0);
        cp_stageB(0);
        cp_commit();
        storeA(0);
    } else {
        cp_stageA(0);
        cp_stageB(0);
        cp_commit();
    }
    // ---- main loop ----
    for (int ci = 0; ci < NC; ci++) {
        cp_wait<0>();
        __syncthreads();
        bool nxt = (ci + 1) < NC;
        if (nxt) {
            if (CONVA) {
                cp_stageB(ci + 1);
                cp_commit();
                loadA_regs(ci + 1);
            } else {
                cp_stageA(ci + 1);
                cp_stageB(ci + 1);
                cp_commit();
            }
        }
        mma_chunk(ci & 1);
        if (CONVA && nxt) storeA(ci + 1);
    }

    // ---- epilogue ----
#pragma unroll
    for (int mt = 0; mt < 2; mt++) {
#pragma unroll
        for (int nt = 0; nt < NT8; nt++) {
#pragma unroll
            for (int half = 0; half < 2; half++) {
                int m = m0 + wm * 32 + mt * 16 + (lane >> 2) + half * 8;
                int n = n0 + wn * WN + nt * 8 + (lane & 3) * 2;
                float v0 = acc[mt][nt][2 * half + 0] * scale;
                float v1 = acc[mt][nt][2 * half + 1] * scale;
                if (bias) {
                    float2 b2 = *(const float2*)(bias + n);
                    v0 += b2.x; v1 += b2.y;
                }
                if (EPI == 1) {
                    v0 = 0.5f * v0 * (1.0f + erff(v0 * 0.70710678118654752f));
                    v1 = 0.5f * v1 * (1.0f + erff(v1 * 0.70710678118654752f));
                }
                if (EPI == 2) {
                    float2 r2 = *(const float2*)(Res + (size_t)m * ldr + n);
                    v0 += r2.x; v1 += r2.y;
                }
                if (OSPLIT) {
                    *(uint32_t*)(Chi + (size_t)m * ldc + n) = hp2(v0, v1);
                    *(uint32_t*)(Clo + (size_t)m * ldc + n) = lp2(v0, v1);
                } else {
                    *(float2*)(C + (size_t)m * ldc + n) = make_float2(v0, v1);
                }
            }
        }
    }
}

// ---------------- split fp32 -> bf16 hi/lo planes -------------------------------
__global__ void splitf_kernel(const float* __restrict__ src, u16* __restrict__ hi,
                              u16* __restrict__ lo, int n4) {
    int i = blockIdx.x * blockDim.x + threadIdx.x;
    if (i >= n4) return;
    float4 v = ((const float4*)src)[i];
    uint2 hh = make_uint2(hp2(v.x, v.y), hp2(v.z, v.w));
    uint2 ll = make_uint2(lp2(v.x, v.y), lp2(v.z, v.w));
    ((uint2*)hi)[i] = hh;
    ((uint2*)lo)[i] = ll;
}

// ---------------- V transpose (bf16 planes): vt[h][d][t] = v[t][h*64+d] ----------
__global__ void vtrans_kernel(const u16* __restrict__ qhi, const u16* __restrict__ qlo,
                              u16* __restrict__ vthi, u16* __restrict__ vtlo) {
    __shared__ uint32_t ts[32][33];
    int h = blockIdx.z;
    int t0 = blockIdx.x * 32, d0 = blockIdx.y * 32;
    int tx = threadIdx.x, ty = threadIdx.y;
#pragma unroll
    for (int i = 0; i < 4; i++) {
        int t = t0 + ty + i * 8;
        size_t base = (size_t)t * (3 * CM) + 2 * CM + h * 64 + d0 + tx;
        ts[ty + i * 8][tx] = (uint32_t)qhi[base] | ((uint32_t)qlo[base] << 16);
    }
    __syncthreads();
#pragma unroll
    for (int i = 0; i < 4; i++) {
        int d = d0 + ty + i * 8;
        uint32_t v = ts[tx][ty + i * 8];
        size_t o = ((size_t)h * 64 + d) * TS + t0 + tx;
        vthi[o] = (u16)(v & 0xffff);
        vtlo[o] = (u16)(v >> 16);
    }
}

// ---------------- LayerNorm -> bf16 hi/lo planes --------------------------------
__global__ void ln_kernel(const float* __restrict__ x, const float* __restrict__ gw,
                          const float* __restrict__ bw, u16* __restrict__ ohi,
                          u16* __restrict__ olo) {
    int row = blockIdx.x;
    int tid = threadIdx.x;
    float4 v = ((const float4*)(x + (size_t)row * CM))[tid];
    float s  = v.x + v.y + v.z + v.w;
    float sq = v.x * v.x + v.y * v.y + v.z * v.z + v.w * v.w;
    __shared__ float rs[8], rq[8];
    __shared__ float s_mu, s_ri;
#pragma unroll
    for (int o = 16; o; o >>= 1) {
        s  += __shfl_xor_sync(0xffffffffu, s, o);
        sq += __shfl_xor_sync(0xffffffffu, sq, o);
    }
    if ((tid & 31) == 0) { rs[tid >> 5] = s; rq[tid >> 5] = sq; }
    __syncthreads();
    if (tid == 0) {
        float ts2 = 0.f, tq = 0.f;
#pragma unroll
        for (int i = 0; i < 8; i++) { ts2 += rs[i]; tq += rq[i]; }
        float mu  = ts2 * (1.0f / CM);
        float var = tq * (1.0f / CM) - mu * mu;
        s_mu = mu;
        s_ri = rsqrtf(var + 1e-5f);
    }
    __syncthreads();
    float mu = s_mu, ri = s_ri;
    float4 g4 = ((const float4*)gw)[tid];
    float4 b4 = ((const float4*)bw)[tid];
    float4 o4;
    o4.x = (v.x - mu) * ri * g4.x + b4.x;
    o4.y = (v.y - mu) * ri * g4.y + b4.y;
    o4.z = (v.z - mu) * ri * g4.z + b4.z;
    o4.w = (v.w - mu) * ri * g4.w + b4.w;
    uint2 hh = make_uint2(hp2(o4.x, o4.y), hp2(o4.z, o4.w));
    uint2 ll = make_uint2(lp2(o4.x, o4.y), lp2(o4.z, o4.w));
    ((uint2*)(ohi + (size_t)row * CM))[tid] = hh;
    ((uint2*)(olo + (size_t)row * CM))[tid] = ll;
}

// ---------------- Row softmax, causal, read-clipped ------------------------------
__global__ void softmax_kernel(float* __restrict__ attn) {
    int q = blockIdx.x, h = blockIdx.y;
    float* row = attn + ((size_t)h * TS + q) * (size_t)TS;
    int n = q + 1;
    int tcnt = (n + 1023) >> 10;   // 1024-col tiles that contain valid data
    int tid = threadIdx.x;
    float4 v[4];
    float lmax = -3.0e38f;
#pragma unroll
    for (int t = 0; t < 4; t++) {
        if (t < tcnt) {
            int j4 = tid + t * 256;
            v[t] = ((const float4*)row)[j4];
            int j = j4 * 4;
            if (j + 0 < n) lmax = fmaxf(lmax, v[t].x);
            if (j + 1 < n) lmax = fmaxf(lmax, v[t].y);
            if (j + 2 < n) lmax = fmaxf(lmax, v[t].z);
            if (j + 3 < n) lmax = fmaxf(lmax, v[t].w);
        }
    }
    __shared__ float red[8];
    __shared__ float bmax, bsum;
#pragma unroll
    for (int o = 16; o; o >>= 1) lmax = fmaxf(lmax, __shfl_xor_sync(0xffffffffu, lmax, o));
    if ((tid & 31) == 0) red[tid >> 5] = lmax;
    __syncthreads();
    if (tid == 0) {
        float m = red[0];
#pragma unroll
        for (int i = 1; i < 8; i++) m = fmaxf(m, red[i]);
        bmax = m;
    }
    __syncthreads();
    float m = bmax;
    float lsum = 0.f;
#pragma unroll
    for (int t = 0; t < 4; t++) {
        if (t < tcnt) {
            int j = (tid + t * 256) * 4;
            v[t].x = (j + 0 < n) ? __expf(v[t].x - m) : 0.0f;
            v[t].y = (j + 1 < n) ? __expf(v[t].y - m) : 0.0f;
            v[t].z = (j + 2 < n) ? __expf(v[t].z - m) : 0.0f;
            v[t].w = (j + 3 < n) ? __expf(v[t].w - m) : 0.0f;
            lsum += v[t].x + v[t].y + v[t].z + v[t].w;
        } else {
            v[t] = make_float4(0.f, 0.f, 0.f, 0.f);
        }
    }
#pragma unroll
    for (int o = 16; o; o >>= 1) lsum += __shfl_xor_sync(0xffffffffu, lsum, o);
    if ((tid & 31) == 0) red[tid >> 5] = lsum;
    __syncthreads();
    if (tid == 0) {
        float s = 0.f;
#pragma unroll
        for (int i = 0; i < 8; i++) s += red[i];
        bsum = s;
    }
    __syncthreads();
    float inv = 1.0f / bsum;
#pragma unroll
    for (int t = 0; t < 4; t++) {
        float4 o4 = make_float4(v[t].x * inv, v[t].y * inv, v[t].z * inv, v[t].w * inv);
        ((float4*)row)[tid + t * 256] = o4;
    }
}

// --------------------------------- launcher -------------------------------------
extern "C" void kernel_launch(void* const* d_in, const int* in_sizes, int n_in,
                              void* d_out, int out_size) {
    const float* x     = (const float*)d_in[0];
    const float* ln1_g = (const float*)d_in[1];
    const float* ln1_b = (const float*)d_in[2];
    const float* w_qkv = (const float*)d_in[3];
    const float* b_qkv = (const float*)d_in[4];
    const float* w_out = (const float*)d_in[5];
    const float* b_out = (const float*)d_in[6];
    const float* ln2_g = (const float*)d_in[7];
    const float* ln2_b = (const float*)d_in[8];
    const float* w1    = (const float*)d_in[9];
    const float* b1    = (const float*)d_in[10];
    const float* w2    = (const float*)d_in[11];
    const float* b2    = (const float*)d_in[12];

    float* out = (float*)d_out;
    size_t attn_elems = (size_t)NH * TS * TS;
    float* attn = out + ((size_t)out_size - attn_elems);

    u16 *ghh, *ghl, *qh, *ql, *vth, *vtl, *cxh, *cxl, *f1h, *f1l;
    u16 *wqh, *wql, *woh, *wol, *w1h, *w1l, *w2h, *w2l;
    float* gx1;
    cudaGetSymbolAddress((void**)&ghh, g_h_hi);
    cudaGetSymbolAddress((void**)&ghl, g_h_lo);
    cudaGetSymbolAddress((void**)&qh, g_qkv_hi);
    cudaGetSymbolAddress((void**)&ql, g_qkv_lo);
    cudaGetSymbolAddress((void**)&vth, g_vt_hi);
    cudaGetSymbolAddress((void**)&vtl, g_vt_lo);
    cudaGetSymbolAddress((void**)&cxh, g_ctx_hi);
    cudaGetSymbolAddress((void**)&cxl, g_ctx_lo);
    cudaGetSymbolAddress((void**)&f1h, g_ff1_hi);
    cudaGetSymbolAddress((void**)&f1l, g_ff1_lo);
    cudaGetSymbolAddress((void**)&wqh, g_wqkv_hi);
    cudaGetSymbolAddress((void**)&wql, g_wqkv_lo);
    cudaGetSymbolAddress((void**)&woh, g_wout_hi);
    cudaGetSymbolAddress((void**)&wol, g_wout_lo);
    cudaGetSymbolAddress((void**)&w1h, g_w1_hi);
    cudaGetSymbolAddress((void**)&w1l, g_w1_lo);
    cudaGetSymbolAddress((void**)&w2h, g_w2_hi);
    cudaGetSymbolAddress((void**)&w2l, g_w2_lo);
    cudaGetSymbolAddress((void**)&gx1, g_x1);

    const int SM128 = 2 * (2 * 128 * 128 + 2 * 128 * 128);  // 131072
    const int SM64  = 2 * (2 * 128 * 128 + 2 * 64 * 128);   //  98304
    cudaFuncSetAttribute((void*)tgemm<128, 0, false, false, false, true >, cudaFuncAttributeMaxDynamicSharedMemorySize, SM128);
    cudaFuncSetAttribute((void*)tgemm<128, 0, true,  false, false, false>, cudaFuncAttributeMaxDynamicSharedMemorySize, SM128);
    cudaFuncSetAttribute((void*)tgemm<64,  0, false, true,  true,  true >, cudaFuncAttributeMaxDynamicSharedMemorySize, SM64);
    cudaFuncSetAttribute((void*)tgemm<128, 2, false, false, false, false>, cudaFuncAttributeMaxDynamicSharedMemorySize, SM128);
    cudaFuncSetAttribute((void*)tgemm<128, 1, false, false, false, true >, cudaFuncAttributeMaxDynamicSharedMemorySize, SM128);

    // 0. weight splits
    splitf_kernel<<<(3 * CM * CM / 4 + 255) / 256, 256>>>(w_qkv, wqh, wql, 3 * CM * CM / 4);
    splitf_kernel<<<(CM * CM / 4 + 255) / 256, 256>>>(w_out, woh, wol, CM * CM / 4);
    splitf_kernel<<<(DFF * CM / 4 + 255) / 256, 256>>>(w1, w1h, w1l, DFF * CM / 4);
    splitf_kernel<<<(CM * DFF / 4 + 255) / 256, 256>>>(w2, w2h, w2l, CM * DFF / 4);
    // 1. LN1 -> planes
    ln_kernel<<<TS, 256>>>(x, ln1_g, ln1_b, ghh, ghl);
    // 2. QKV -> qkv planes
    tgemm<128, 0, false, false, false, true><<<dim3(24, 32, 1), 256, SM128>>>(
        ghh, ghl, nullptr, CM, 0, wqh, wql, CM, 0,
        nullptr, qh, ql, 3 * CM, 0, b_qkv, nullptr, 0, CM, 1.0f);
    // 3. V transpose (bf16 planes)
    vtrans_kernel<<<dim3(TS / 32, 2, NH), dim3(32, 8)>>>(qh, ql, vth, vtl);
    // 4. Scores: Q @ K^T / 8 -> attn fp32 (causal skip)
    tgemm<128, 0, true, false, false, false><<<dim3(32, 32, NH), 256, SM128>>>(
        qh, ql, nullptr, 3 * CM, 64, qh + CM, ql + CM, 3 * CM, 64,
        attn, nullptr, nullptr, TS, (long long)TS * TS, nullptr, nullptr, 0, 64, 0.125f);
    // 5. Softmax (causal zero-fill, clipped reads)
    softmax_kernel<<<dim3(TS, NH), 256>>>(attn);
    // 6. PV: attn(fp32, conv in-kernel) @ Vt^T -> ctx planes (causal K clamp)
    tgemm<64, 0, false, true, true, true><<<dim3(1, 32, NH), 256, SM64>>>(
        nullptr, nullptr, attn, TS, (long long)TS * TS, vth, vtl, TS, (long long)64 * TS,
        nullptr, cxh, cxl, CM, 64, nullptr, nullptr, 0, TS, 1.0f);
    // 7. Out projection + residual(x) -> x1 fp32
    tgemm<128, 2, false, false, false, false><<<dim3(8, 32, 1), 256, SM128>>>(
        cxh, cxl, nullptr, CM, 0, woh, wol, CM, 0,
        gx1, nullptr, nullptr, CM, 0, b_out, x, CM, CM, 1.0f);
    // 8. LN2 -> planes
    ln_kernel<<<TS, 256>>>(gx1, ln2_g, ln2_b, ghh, ghl);
    // 9. FF1 + GELU -> ff1 planes
    tgemm<128, 1, false, false, false, true><<<dim3(32, 32, 1), 256, SM128>>>(
        ghh, ghl, nullptr, CM, 0, w1h, w1l, CM, 0,
        nullptr, f1h, f1l, DFF, 0, b1, nullptr, 0, CM, 1.0f);
    // 10. FF2 + residual(x1) -> final x
    tgemm<128, 2, false, false, false, false><<<dim3(8, 32, 1), 256, SM128>>>(
        f1h, f1l, nullptr, DFF, 0, w2h, w2l, DFF, 0,
        out, nullptr, nullptr, CM, 0, b2, gx1, CM, DFF, 1.0f);
}

// round 10
// speedup vs baseline: 1.0007x; 1.0007x over previous
#include <cuda_runtime.h>
#include <cuda_bf16.h>
#include <cstdint>
#include <math.h>

#define TS 4096
#define CM 1024
#define NH 16
#define DFF 4096

typedef unsigned short u16;

// ----------------------------- scratch (no allocs) -----------------------------
__device__ __align__(256) u16 g_h_hi[TS * CM];
__device__ __align__(256) u16 g_h_lo[TS * CM];
__device__ __align__(256) u16 g_qkv_hi[TS * 3 * CM];
__device__ __align__(256) u16 g_qkv_lo[TS * 3 * CM];
__device__ __align__(256) u16 g_vt_hi[NH * 64 * TS];
__device__ __align__(256) u16 g_vt_lo[NH * 64 * TS];
__device__ __align__(256) u16 g_ctx_hi[TS * CM];
__device__ __align__(256) u16 g_ctx_lo[TS * CM];
__device__ __align__(256) u16 g_ff1_hi[TS * DFF];
__device__ __align__(256) u16 g_ff1_lo[TS * DFF];
__device__ __align__(256) u16 g_wqkv_hi[3 * CM * CM];
__device__ __align__(256) u16 g_wqkv_lo[3 * CM * CM];
__device__ __align__(256) u16 g_wout_hi[CM * CM];
__device__ __align__(256) u16 g_wout_lo[CM * CM];
__device__ __align__(256) u16 g_w1_hi[DFF * CM];
__device__ __align__(256) u16 g_w1_lo[DFF * CM];
__device__ __align__(256) u16 g_w2_hi[CM * DFF];
__device__ __align__(256) u16 g_w2_lo[CM * DFF];
__device__ __align__(256) float g_x1[TS * CM];

// ----------------------------- helpers -----------------------------------------
__device__ __forceinline__ uint32_t smem_u32(const void* p) {
    uint32_t a;
    asm("{ .reg .u64 t; cvta.to.shared.u64 t, %1; cvt.u32.u64 %0, t; }" : "=r"(a) : "l"(p));
    return a;
}
__device__ __forceinline__ uint32_t sw128(uint32_t off) { return off ^ ((off >> 3) & 0x70); }
__device__ __forceinline__ float thi(float x) {
    return __uint_as_float(__float_as_uint(x) & 0xffff0000u);
}
__device__ __forceinline__ uint32_t cv2(float e0, float e1) {  // low half = bf16(e0)
    uint32_t r;
    asm("cvt.rn.bf16x2.f32 %0, %1, %2;" : "=r"(r) : "f"(e1), "f"(e0));
    return r;
}
__device__ __forceinline__ uint32_t hp2(float v0, float v1) {  // (trunc16(v0),trunc16(v1))
    return __byte_perm(__float_as_uint(v0), __float_as_uint(v1), 0x7632);
}
__device__ __forceinline__ uint32_t lp2(float v0, float v1) {
    return cv2(v0 - thi(v0), v1 - thi(v1));
}
__device__ __forceinline__ void conv8(float4 a, float4 b, uint4& hi, uint4& lo) {
    hi.x = hp2(a.x, a.y); hi.y = hp2(a.z, a.w);
    hi.z = hp2(b.x, b.y); hi.w = hp2(b.z, b.w);
    lo.x = lp2(a.x, a.y); lo.y = lp2(a.z, a.w);
    lo.z = lp2(b.x, b.y); lo.w = lp2(b.z, b.w);
}
__device__ __forceinline__ void cp16(uint32_t dst, const void* src) {
    asm volatile("cp.async.cg.shared.global [%0], [%1], 16;" :: "r"(dst), "l"(src));
}
__device__ __forceinline__ void cp_commit() {
    asm volatile("cp.async.commit_group;" ::: "memory");
}
template <int N>
__device__ __forceinline__ void cp_wait() {
    asm volatile("cp.async.wait_group %0;" :: "n"(N) : "memory");
}
__device__ __forceinline__ void ldsm4(uint32_t* r, uint32_t addr) {
    asm volatile("ldmatrix.sync.aligned.m8n8.x4.shared.b16 {%0,%1,%2,%3}, [%4];"
                 : "=r"(r[0]), "=r"(r[1]), "=r"(r[2]), "=r"(r[3]) : "r"(addr));
}
__device__ __forceinline__ void mma16816(float* c, const uint32_t* a, uint32_t b0, uint32_t b1) {
    asm volatile(
        "mma.sync.aligned.m16n8k16.row.col.f32.bf16.bf16.f32 "
        "{%0,%1,%2,%3}, {%4,%5,%6,%7}, {%8,%9}, {%0,%1,%2,%3};"
        : "+f"(c[0]), "+f"(c[1]), "+f"(c[2]), "+f"(c[3])
        : "r"(a[0]), "r"(a[1]), "r"(a[2]), "r"(a[3]), "r"(b0), "r"(b1));
}

// ------------------- warp-MMA GEMM on pre-split bf16 planes ---------------------
// C[M,N] = scale*(A @ B^T) + epi.  A: hi/lo planes [M,K] (or fp32 if CONVA),
// B: hi/lo planes [N,K].  BM=128, BK=64, 3-pass split accumulation.
// EPI: 0 none, 1 GELU, 2 +residual.  OSPLIT: write hi/lo bf16 planes instead of fp32.
template <int BN, int EPI, bool CSKIP, bool CKLIM, bool CONVA, bool OSPLIT>
__global__ __launch_bounds__(256, 1) void tgemm(
    const u16* __restrict__ Ahi, const u16* __restrict__ Alo,
    const float* __restrict__ Af, int lda, long long sAh,
    const u16* __restrict__ Bhi, const u16* __restrict__ Blo, int ldb, long long sBh,
    float* __restrict__ C, u16* __restrict__ Chi, u16* __restrict__ Clo,
    int ldc, long long sCh,
    const float* __restrict__ bias, const float* __restrict__ Res, int ldr,
    int K, float scale) {
    constexpr int SZAp = 128 * 128;          // one A plane: 128 rows x 128B
    constexpr int SZBp = BN * 128;
    constexpr int STAGE = 2 * SZAp + 2 * SZBp;
    constexpr int NBI = (BN * 8) / 256;      // 16B chunks per thread per B plane
    constexpr int WN = BN / 2;
    constexpr int NT8 = WN / 8;
    extern __shared__ char smem[];

    int m0 = blockIdx.y * 128;
    int n0 = blockIdx.x * BN;
    if (CSKIP && n0 >= m0 + 128) return;
    int h = blockIdx.z;
    if (CONVA) Af += (size_t)h * sAh;
    else { Ahi += (size_t)h * sAh; Alo += (size_t)h * sAh; }
    Bhi += (size_t)h * sBh;
    Blo += (size_t)h * sBh;
    // per-head output offset (THE R6 BUG: this was missing)
    if (OSPLIT) { Chi += (size_t)h * sCh; Clo += (size_t)h * sCh; }
    else        { C   += (size_t)h * sCh; }
    int kend = CKLIM ? ((m0 + 128 < K) ? (m0 + 128) : K) : K;
    int NC = kend >> 6;

    int tid = threadIdx.x;
    int lane = tid & 31, wid = tid >> 5;
    int wm = wid & 3, wn = wid >> 2;
    uint32_t sb = smem_u32(smem);

    float acc[2][NT8][4];
#pragma unroll
    for (int i = 0; i < 2; i++)
#pragma unroll
        for (int j = 0; j < NT8; j++)
#pragma unroll
            for (int q = 0; q < 4; q++) acc[i][j][q] = 0.f;

    int crow = tid >> 3, cchk = tid & 7;          // cp.async thread mapping

    float4 ra[4][2];                              // CONVA register staging

    auto cp_stageB = [&](int ci) {
        int b = ci & 1;
        uint32_t base = sb + b * STAGE + 2 * SZAp;
        int k0 = ci * 64;
#pragma unroll
        for (int i = 0; i < NBI; i++) {
            int row = crow + i * 32;
            uint32_t off = sw128(row * 128 + cchk * 16);
            const u16* s = Bhi + (size_t)(n0 + row) * ldb + k0 + cchk * 8;
            cp16(base + off, s);
        }
#pragma unroll
        for (int i = 0; i < NBI; i++) {
            int row = crow + i * 32;
            uint32_t off = sw128(row * 128 + cchk * 16);
            const u16* s = Blo + (size_t)(n0 + row) * ldb + k0 + cchk * 8;
            cp16(base + SZBp + off, s);
        }
    };
    auto cp_stageA = [&](int ci) {
        int b = ci & 1;
        uint32_t base = sb + b * STAGE;
        int k0 = ci * 64;
#pragma unroll
        for (int i = 0; i < 4; i++) {
            int row = crow + i * 32;
            uint32_t off = sw128(row * 128 + cchk * 16);
            cp16(base + off, Ahi + (size_t)(m0 + row) * lda + k0 + cchk * 8);
        }
#pragma unroll
        for (int i = 0; i < 4; i++) {
            int row = crow + i * 32;
            uint32_t off = sw128(row * 128 + cchk * 16);
            cp16(base + SZAp + off, Alo + (size_t)(m0 + row) * lda + k0 + cchk * 8);
        }
    };
    auto loadA_regs = [&](int ci) {
        int k0 = ci * 64;
#pragma unroll
        for (int i = 0; i < 4; i++) {
            int idx = tid + i * 256;
            int row = idx >> 3, g = idx & 7;
            const float* s = Af + (size_t)(m0 + row) * lda + k0 + g * 8;
            ra[i][0] = *(const float4*)s;
            ra[i][1] = *(const float4*)(s + 4);
        }
    };
    auto storeA = [&](int ci) {
        int b = ci & 1;
        char* bufp = smem + b * STAGE;
#pragma unroll
        for (int i = 0; i < 4; i++) {
            int idx = tid + i * 256;
            int row = idx >> 3, g = idx & 7;
            uint4 hi, lo;
            conv8(ra[i][0], ra[i][1], hi, lo);
            uint32_t off = sw128(row * 128 + g * 16);
            *(uint4*)(bufp + off) = hi;
            *(uint4*)(bufp + SZAp + off) = lo;
        }
    };
    auto mma_chunk = [&](int b) {
        uint32_t bA = sb + b * STAGE;
        uint32_t bB = bA + 2 * SZAp;
        int g = lane >> 3;
#pragma unroll
        for (int ks = 0; ks < 4; ks++) {
            int kb = ks * 32;
            uint32_t ahi[2][4], alo[2][4];
#pragma unroll
            for (int mt = 0; mt < 2; mt++) {
                int row = wm * 32 + mt * 16 + (g & 1) * 8 + (lane & 7);
                uint32_t off = sw128(row * 128 + kb + (g >> 1) * 16);
                ldsm4(ahi[mt], bA + off);
                ldsm4(alo[mt], bA + SZAp + off);
            }
#pragma unroll
            for (int nt2 = 0; nt2 < NT8 / 2; nt2++) {
                int row = wn * WN + nt2 * 16 + (g >> 1) * 8 + (lane & 7);
                uint32_t off = sw128(row * 128 + kb + (g & 1) * 16);
                uint32_t bhi[4], blo[4];
                ldsm4(bhi, bB + off);
                ldsm4(blo, bB + SZBp + off);
#pragma unroll
                for (int mt = 0; mt < 2; mt++) {
#pragma unroll
                    for (int j = 0; j < 2; j++) {
                        float* c = acc[mt][nt2 * 2 + j];
                        mma16816(c, ahi[mt], bhi[2 * j], bhi[2 * j + 1]);
                        mma16816(c, ahi[mt], blo[2 * j], blo[2 * j + 1]);
                        mma16816(c, alo[mt], bhi[2 * j], bhi[2 * j + 1]);
                    }
                }
            }
        }
    };

    // ---- prologue ----
    if (CONVA) {
        loadA_regs(0);
        cp_stageB(0);
        cp_commit();
        storeA(0);
    } else {
        cp_stageA(0);
        cp_stageB(0);
        cp_commit();
    }
    // ---- main loop ----
    for (int ci = 0; ci < NC; ci++) {
        cp_wait<0>();
        __syncthreads();
        bool nxt = (ci + 1) < NC;
        if (nxt) {
            if (CONVA) {
                cp_stageB(ci + 1);
                cp_commit();
                loadA_regs(ci + 1);
            } else {
                cp_stageA(ci + 1);
                cp_stageB(ci + 1);
                cp_commit();
            }
        }
        mma_chunk(ci & 1);
        if (CONVA && nxt) storeA(ci + 1);
    }

    // ---- epilogue ----
#pragma unroll
    for (int mt = 0; mt < 2; mt++) {
#pragma unroll
        for (int nt = 0; nt < NT8; nt++) {
#pragma unroll
            for (int half = 0; half < 2; half++) {
                int m = m0 + wm * 32 + mt * 16 + (lane >> 2) + half * 8;
                int n = n0 + wn * WN + nt * 8 + (lane & 3) * 2;
                float v0 = acc[mt][nt][2 * half + 0] * scale;
                float v1 = acc[mt][nt][2 * half + 1] * scale;
                if (bias) {
                    float2 b2 = *(const float2*)(bias + n);
                    v0 += b2.x; v1 += b2.y;
                }
                if (EPI == 1) {
                    v0 = 0.5f * v0 * (1.0f + erff(v0 * 0.70710678118654752f));
                    v1 = 0.5f * v1 * (1.0f + erff(v1 * 0.70710678118654752f));
                }
                if (EPI == 2) {
                    float2 r2 = *(const float2*)(Res + (size_t)m * ldr + n);
                    v0 += r2.x; v1 += r2.y;
                }
                if (OSPLIT) {
                    *(uint32_t*)(Chi + (size_t)m * ldc + n) = hp2(v0, v1);
                    *(uint32_t*)(Clo + (size_t)m * ldc + n) = lp2(v0, v1);
                } else {
                    *(float2*)(C + (size_t)m * ldc + n) = make_float2(v0, v1);
                }
            }
        }
    }
}

// ---------------- split fp32 -> bf16 hi/lo planes -------------------------------
__global__ void splitf_kernel(const float* __restrict__ src, u16* __restrict__ hi,
                              u16* __restrict__ lo, int n4) {
    int i = blockIdx.x * blockDim.x + threadIdx.x;
    if (i >= n4) return;
    float4 v = ((const float4*)src)[i];
    uint2 hh = make_uint2(hp2(v.x, v.y), hp2(v.z, v.w));
    uint2 ll = make_uint2(lp2(v.x, v.y), lp2(v.z, v.w));
    ((uint2*)hi)[i] = hh;
    ((uint2*)lo)[i] = ll;
}

// ---------------- V transpose (bf16 planes): vt[h][d][t] = v[t][h*64+d] ----------
__global__ void vtrans_kernel(const u16* __restrict__ qhi, const u16* __restrict__ qlo,
                              u16* __restrict__ vthi, u16* __restrict__ vtlo) {
    __shared__ uint32_t ts[32][33];
    int h = blockIdx.z;
    int t0 = blockIdx.x * 32, d0 = blockIdx.y * 32;
    int tx = threadIdx.x, ty = threadIdx.y;
#pragma unroll
    for (int i = 0; i < 4; i++) {
        int t = t0 + ty + i * 8;
        size_t base = (size_t)t * (3 * CM) + 2 * CM + h * 64 + d0 + tx;
        ts[ty + i * 8][tx] = (uint32_t)qhi[base] | ((uint32_t)qlo[base] << 16);
    }
    __syncthreads();
#pragma unroll
    for (int i = 0; i < 4; i++) {
        int d = d0 + ty + i * 8;
        uint32_t v = ts[tx][ty + i * 8];
        size_t o = ((size_t)h * 64 + d) * TS + t0 + tx;
        vthi[o] = (u16)(v & 0xffff);
        vtlo[o] = (u16)(v >> 16);
    }
}

// ---------------- LayerNorm -> bf16 hi/lo planes --------------------------------
__global__ void ln_kernel(const float* __restrict__ x, const float* __restrict__ gw,
                          const float* __restrict__ bw, u16* __restrict__ ohi,
                          u16* __restrict__ olo) {
    int row = blockIdx.x;
    int tid = threadIdx.x;
    float4 v = ((const float4*)(x + (size_t)row * CM))[tid];
    float s  = v.x + v.y + v.z + v.w;
    float sq = v.x * v.x + v.y * v.y + v.z * v.z + v.w * v.w;
    __shared__ float rs[8], rq[8];
    __shared__ float s_mu, s_ri;
#pragma unroll
    for (int o = 16; o; o >>= 1) {
        s  += __shfl_xor_sync(0xffffffffu, s, o);
        sq += __shfl_xor_sync(0xffffffffu, sq, o);
    }
    if ((tid & 31) == 0) { rs[tid >> 5] = s; rq[tid >> 5] = sq; }
    __syncthreads();
    if (tid == 0) {
        float ts2 = 0.f, tq = 0.f;
#pragma unroll
        for (int i = 0; i < 8; i++) { ts2 += rs[i]; tq += rq[i]; }
        float mu  = ts2 * (1.0f / CM);
        float var = tq * (1.0f / CM) - mu * mu;
        s_mu = mu;
        s_ri = rsqrtf(var + 1e-5f);
    }
    __syncthreads();
    float mu = s_mu, ri = s_ri;
    float4 g4 = ((const float4*)gw)[tid];
    float4 b4 = ((const float4*)bw)[tid];
    float4 o4;
    o4.x = (v.x - mu) * ri * g4.x + b4.x;
    o4.y = (v.y - mu) * ri * g4.y + b4.y;
    o4.z = (v.z - mu) * ri * g4.z + b4.z;
    o4.w = (v.w - mu) * ri * g4.w + b4.w;
    uint2 hh = make_uint2(hp2(o4.x, o4.y), hp2(o4.z, o4.w));
    uint2 ll = make_uint2(lp2(o4.x, o4.y), lp2(o4.z, o4.w));
    ((uint2*)(ohi + (size_t)row * CM))[tid] = hh;
    ((uint2*)(olo + (size_t)row * CM))[tid] = ll;
}

// ---------------- Row softmax, causal, read-clipped ------------------------------
__global__ void softmax_kernel(float* __restrict__ attn) {
    int q = blockIdx.x, h = blockIdx.y;
    float* row = attn + ((size_t)h * TS + q) * (size_t)TS;
    int n = q + 1;
    int tcnt = (n + 1023) >> 10;   // 1024-col tiles that contain valid data
    int tid = threadIdx.x;
    float4 v[4];
    float lmax = -3.0e38f;
#pragma unroll
    for (int t = 0; t < 4; t++) {
        if (t < tcnt) {
            int j4 = tid + t * 256;
            v[t] = ((const float4*)row)[j4];
            int j = j4 * 4;
            if (j + 0 < n) lmax = fmaxf(lmax, v[t].x);
            if (j + 1 < n) lmax = fmaxf(lmax, v[t].y);
            if (j + 2 < n) lmax = fmaxf(lmax, v[t].z);
            if (j + 3 < n) lmax = fmaxf(lmax, v[t].w);
        }
    }
    __shared__ float red[8];
    __shared__ float bmax, bsum;
#pragma unroll
    for (int o = 16; o; o >>= 1) lmax = fmaxf(lmax, __shfl_xor_sync(0xffffffffu, lmax, o));
    if ((tid & 31) == 0) red[tid >> 5] = lmax;
    __syncthreads();
    if (tid == 0) {
        float m = red[0];
#pragma unroll
        for (int i = 1; i < 8; i++) m = fmaxf(m, red[i]);
        bmax = m;
    }
    __syncthreads();
    float m = bmax;
    float lsum = 0.f;
#pragma unroll
    for (int t = 0; t < 4; t++) {
        if (t < tcnt) {
            int j = (tid + t * 256) * 4;
            v[t].x = (j + 0 < n) ? __expf(v[t].x - m) : 0.0f;
            v[t].y = (j + 1 < n) ? __expf(v[t].y - m) : 0.0f;
            v[t].z = (j + 2 < n) ? __expf(v[t].z - m) : 0.0f;
            v[t].w = (j + 3 < n) ? __expf(v[t].w - m) : 0.0f;
            lsum += v[t].x + v[t].y + v[t].z + v[t].w;
        } else {
            v[t] = make_float4(0.f, 0.f, 0.f, 0.f);
        }
    }
#pragma unroll
    for (int o = 16; o; o >>= 1) lsum += __shfl_xor_sync(0xffffffffu, lsum, o);
    if ((tid & 31) == 0) red[tid >> 5] = lsum;
    __syncthreads();
    if (tid == 0) {
        float s = 0.f;
#pragma unroll
        for (int i = 0; i < 8; i++) s += red[i];
        bsum = s;
    }
    __syncthreads();
    float inv = 1.0f / bsum;
#pragma unroll
    for (int t = 0; t < 4; t++) {
        float4 o4 = make_float4(v[t].x * inv, v[t].y * inv, v[t].z * inv, v[t].w * inv);
        ((float4*)row)[tid + t * 256] = o4;
    }
}

// --------------------------------- launcher -------------------------------------
extern "C" void kernel_launch(void* const* d_in, const int* in_sizes, int n_in,
                              void* d_out, int out_size) {
    const float* x     = (const float*)d_in[0];
    const float* ln1_g = (const float*)d_in[1];
    const float* ln1_b = (const float*)d_in[2];
    const float* w_qkv = (const float*)d_in[3];
    const float* b_qkv = (const float*)d_in[4];
    const float* w_out = (const float*)d_in[5];
    const float* b_out = (const float*)d_in[6];
    const float* ln2_g = (const float*)d_in[7];
    const float* ln2_b = (const float*)d_in[8];
    const float* w1    = (const float*)d_in[9];
    const float* b1    = (const float*)d_in[10];
    const float* w2    = (const float*)d_in[11];
    const float* b2    = (const float*)d_in[12];

    float* out = (float*)d_out;
    size_t attn_elems = (size_t)NH * TS * TS;
    float* attn = out + ((size_t)out_size - attn_elems);

    u16 *ghh, *ghl, *qh, *ql, *vth, *vtl, *cxh, *cxl, *f1h, *f1l;
    u16 *wqh, *wql, *woh, *wol, *w1h, *w1l, *w2h, *w2l;
    float* gx1;
    cudaGetSymbolAddress((void**)&ghh, g_h_hi);
    cudaGetSymbolAddress((void**)&ghl, g_h_lo);
    cudaGetSymbolAddress((void**)&qh, g_qkv_hi);
    cudaGetSymbolAddress((void**)&ql, g_qkv_lo);
    cudaGetSymbolAddress((void**)&vth, g_vt_hi);
    cudaGetSymbolAddress((void**)&vtl, g_vt_lo);
    cudaGetSymbolAddress((void**)&cxh, g_ctx_hi);
    cudaGetSymbolAddress((void**)&cxl, g_ctx_lo);
    cudaGetSymbolAddress((void**)&f1h, g_ff1_hi);
    cudaGetSymbolAddress((void**)&f1l, g_ff1_lo);
    cudaGetSymbolAddress((void**)&wqh, g_wqkv_hi);
    cudaGetSymbolAddress((void**)&wql, g_wqkv_lo);
    cudaGetSymbolAddress((void**)&woh, g_wout_hi);
    cudaGetSymbolAddress((void**)&wol, g_wout_lo);
    cudaGetSymbolAddress((void**)&w1h, g_w1_hi);
    cudaGetSymbolAddress((void**)&w1l, g_w1_lo);
    cudaGetSymbolAddress((void**)&w2h, g_w2_hi);
    cudaGetSymbolAddress((void**)&w2l, g_w2_lo);
    cudaGetSymbolAddress((void**)&gx1, g_x1);

    const int SM128 = 2 * (2 * 128 * 128 + 2 * 128 * 128);  // 131072
    const int SM64  = 2 * (2 * 128 * 128 + 2 * 64 * 128);   //  98304
    cudaFuncSetAttribute((void*)tgemm<128, 0, false, false, false, true >, cudaFuncAttributeMaxDynamicSharedMemorySize, SM128);
    cudaFuncSetAttribute((void*)tgemm<128, 0, true,  false, false, false>, cudaFuncAttributeMaxDynamicSharedMemorySize, SM128);
    cudaFuncSetAttribute((void*)tgemm<64,  0, false, true,  true,  true >, cudaFuncAttributeMaxDynamicSharedMemorySize, SM64);
    cudaFuncSetAttribute((void*)tgemm<128, 2, false, false, false, false>, cudaFuncAttributeMaxDynamicSharedMemorySize, SM128);
    cudaFuncSetAttribute((void*)tgemm<128, 1, false, false, false, true >, cudaFuncAttributeMaxDynamicSharedMemorySize, SM128);

    // 0. weight splits
    splitf_kernel<<<(3 * CM * CM / 4 + 255) / 256, 256>>>(w_qkv, wqh, wql, 3 * CM * CM / 4);
    splitf_kernel<<<(CM * CM / 4 + 255) / 256, 256>>>(w_out, woh, wol, CM * CM / 4);
    splitf_kernel<<<(DFF * CM / 4 + 255) / 256, 256>>>(w1, w1h, w1l, DFF * CM / 4);
    splitf_kernel<<<(CM * DFF / 4 + 255) / 256, 256>>>(w2, w2h, w2l, CM * DFF / 4);
    // 1. LN1 -> planes
    ln_kernel<<<TS, 256>>>(x, ln1_g, ln1_b, ghh, ghl);
    // 2. QKV -> qkv planes
    tgemm<128, 0, false, false, false, true><<<dim3(24, 32, 1), 256, SM128>>>(
        ghh, ghl, nullptr, CM, 0, wqh, wql, CM, 0,
        nullptr, qh, ql, 3 * CM, 0, b_qkv, nullptr, 0, CM, 1.0f);
    // 3. V transpose (bf16 planes)
    vtrans_kernel<<<dim3(TS / 32, 2, NH), dim3(32, 8)>>>(qh, ql, vth, vtl);
    // 4. Scores: Q @ K^T / 8 -> attn fp32 (causal skip)
    tgemm<128, 0, true, false, false, false><<<dim3(32, 32, NH), 256, SM128>>>(
        qh, ql, nullptr, 3 * CM, 64, qh + CM, ql + CM, 3 * CM, 64,
        attn, nullptr, nullptr, TS, (long long)TS * TS, nullptr, nullptr, 0, 64, 0.125f);
    // 5. Softmax (causal zero-fill, clipped reads)
    softmax_kernel<<<dim3(TS, NH), 256>>>(attn);
    // 6. PV: attn(fp32, conv in-kernel) @ Vt^T -> ctx planes (causal K clamp)
    tgemm<64, 0, false, true, true, true><<<dim3(1, 32, NH), 256, SM64>>>(
        nullptr, nullptr, attn, TS, (long long)TS * TS, vth, vtl, TS, (long long)64 * TS,
        nullptr, cxh, cxl, CM, 64, nullptr, nullptr, 0, TS, 1.0f);
    // 7. Out projection + residual(x) -> x1 fp32
    tgemm<128, 2, false, false, false, false><<<dim3(8, 32, 1), 256, SM128>>>(
        cxh, cxl, nullptr, CM, 0, woh, wol, CM, 0,
        gx1, nullptr, nullptr, CM, 0, b_out, x, CM, CM, 1.0f);
    // 8. LN2 -> planes
    ln_kernel<<<TS, 256>>>(gx1, ln2_g, ln2_b, ghh, ghl);
    // 9. FF1 + GELU -> ff1 planes
    tgemm<128, 1, false, false, false, true><<<dim3(32, 32, 1), 256, SM128>>>(
        ghh, ghl, nullptr, CM, 0, w1h, w1l, CM, 0,
        nullptr, f1h, f1l, DFF, 0, b1, nullptr, 0, CM, 1.0f);
    // 10. FF2 + residual(x1) -> final x
    tgemm<128, 2, false, false, false, false><<<dim3(8, 32, 1), 256, SM128>>>(
        f1h, f1l, nullptr, DFF, 0, w2h, w2l, DFF, 0,
        out, nullptr, nullptr, CM, 0, b2, gx1, CM, DFF, 1.0f);
}

// round 11
// speedup vs baseline: 1.0017x; 1.0010x over previous
#include <cuda_runtime.h>
#include <cuda_bf16.h>
#include <cstdint>
#include <math.h>

#define TS 4096
#define CM 1024
#define NH 16
#define DFF 4096

typedef unsigned short u16;

// ----------------------------- scratch (no allocs) -----------------------------
__device__ __align__(256) u16 g_h_hi[TS * CM];
__device__ __align__(256) u16 g_h_lo[TS * CM];
__device__ __align__(256) u16 g_qkv_hi[TS * 3 * CM];
__device__ __align__(256) u16 g_qkv_lo[TS * 3 * CM];
__device__ __align__(256) u16 g_vt_hi[NH * 64 * TS];
__device__ __align__(256) u16 g_vt_lo[NH * 64 * TS];
__device__ __align__(256) u16 g_ctx_hi[TS * CM];
__device__ __align__(256) u16 g_ctx_lo[TS * CM];
__device__ __align__(256) u16 g_ff1_hi[TS * DFF];
__device__ __align__(256) u16 g_ff1_lo[TS * DFF];
__device__ __align__(256) u16 g_wqkv_hi[3 * CM * CM];
__device__ __align__(256) u16 g_wqkv_lo[3 * CM * CM];
__device__ __align__(256) u16 g_wout_hi[CM * CM];
__device__ __align__(256) u16 g_wout_lo[CM * CM];
__device__ __align__(256) u16 g_w1_hi[DFF * CM];
__device__ __align__(256) u16 g_w1_lo[DFF * CM];
__device__ __align__(256) u16 g_w2_hi[CM * DFF];
__device__ __align__(256) u16 g_w2_lo[CM * DFF];
__device__ __align__(256) float g_x1[TS * CM];

// ----------------------------- helpers -----------------------------------------
__device__ __forceinline__ uint32_t smem_u32(const void* p) {
    uint32_t a;
    asm("{ .reg .u64 t; cvta.to.shared.u64 t, %1; cvt.u32.u64 %0, t; }" : "=r"(a) : "l"(p));
    return a;
}
__device__ __forceinline__ uint32_t sw128(uint32_t off) { return off ^ ((off >> 3) & 0x70); }
__device__ __forceinline__ float thi(float x) {
    return __uint_as_float(__float_as_uint(x) & 0xffff0000u);
}
__device__ __forceinline__ uint32_t cv2(float e0, float e1) {  // low half = bf16(e0)
    uint32_t r;
    asm("cvt.rn.bf16x2.f32 %0, %1, %2;" : "=r"(r) : "f"(e1), "f"(e0));
    return r;
}
__device__ __forceinline__ uint32_t hp2(float v0, float v1) {  // (trunc16(v0),trunc16(v1))
    return __byte_perm(__float_as_uint(v0), __float_as_uint(v1), 0x7632);
}
__device__ __forceinline__ uint32_t lp2(float v0, float v1) {
    return cv2(v0 - thi(v0), v1 - thi(v1));
}
__device__ __forceinline__ void conv8(float4 a, float4 b, uint4& hi, uint4& lo) {
    hi.x = hp2(a.x, a.y); hi.y = hp2(a.z, a.w);
    hi.z = hp2(b.x, b.y); hi.w = hp2(b.z, b.w);
    lo.x = lp2(a.x, a.y); lo.y = lp2(a.z, a.w);
    lo.z = lp2(b.x, b.y); lo.w = lp2(b.z, b.w);
}
__device__ __forceinline__ void cp16(uint32_t dst, const void* src) {
    asm volatile("cp.async.cg.shared.global [%0], [%1], 16;" :: "r"(dst), "l"(src));
}
__device__ __forceinline__ void cp_commit() {
    asm volatile("cp.async.commit_group;" ::: "memory");
}
template <int N>
__device__ __forceinline__ void cp_wait() {
    asm volatile("cp.async.wait_group %0;" :: "n"(N) : "memory");
}
__device__ __forceinline__ void ldsm4(uint32_t* r, uint32_t addr) {
    asm volatile("ldmatrix.sync.aligned.m8n8.x4.shared.b16 {%0,%1,%2,%3}, [%4];"
                 : "=r"(r[0]), "=r"(r[1]), "=r"(r[2]), "=r"(r[3]) : "r"(addr));
}
__device__ __forceinline__ void mma16816(float* c, const uint32_t* a, uint32_t b0, uint32_t b1) {
    asm volatile(
        "mma.sync.aligned.m16n8k16.row.col.f32.bf16.bf16.f32 "
        "{%0,%1,%2,%3}, {%4,%5,%6,%7}, {%8,%9}, {%0,%1,%2,%3};"
        : "+f"(c[0]), "+f"(c[1]), "+f"(c[2]), "+f"(c[3])
        : "r"(a[0]), "r"(a[1]), "r"(a[2]), "r"(a[3]), "r"(b0), "r"(b1));
}

// ------------------- warp-MMA GEMM on pre-split bf16 planes ---------------------
// C[M,N] = scale*(A @ B^T) + epi.  A: hi/lo planes [M,K] (or fp32 if CONVA),
// B: hi/lo planes [N,K].  BM=128, BK=64, 3-pass split accumulation.
// EPI: 0 none, 1 GELU, 2 +residual.  OSPLIT: write hi/lo bf16 planes instead of fp32.
template <int BN, int EPI, bool CSKIP, bool CKLIM, bool CONVA, bool OSPLIT>
__global__ __launch_bounds__(256, 1) void tgemm(
    const u16* __restrict__ Ahi, const u16* __restrict__ Alo,
    const float* __restrict__ Af, int lda, long long sAh,
    const u16* __restrict__ Bhi, const u16* __restrict__ Blo, int ldb, long long sBh,
    float* __restrict__ C, u16* __restrict__ Chi, u16* __restrict__ Clo,
    int ldc, long long sCh,
    const float* __restrict__ bias, const float* __restrict__ Res, int ldr,
    int K, float scale) {
    constexpr int SZAp = 128 * 128;          // one A plane: 128 rows x 128B
    constexpr int SZBp = BN * 128;
    constexpr int STAGE = 2 * SZAp + 2 * SZBp;
    constexpr int NBI = (BN * 8) / 256;      // 16B chunks per thread per B plane
    constexpr int WN = BN / 2;
    constexpr int NT8 = WN / 8;
    extern __shared__ char smem[];

    int m0 = blockIdx.y * 128;
    int n0 = blockIdx.x * BN;
    if (CSKIP && n0 >= m0 + 128) return;
    int h = blockIdx.z;
    if (CONVA) Af += (size_t)h * sAh;
    else { Ahi += (size_t)h * sAh; Alo += (size_t)h * sAh; }
    Bhi += (size_t)h * sBh;
    Blo += (size_t)h * sBh;
    // per-head output offset (THE R6 BUG: this was missing)
    if (OSPLIT) { Chi += (size_t)h * sCh; Clo += (size_t)h * sCh; }
    else        { C   += (size_t)h * sCh; }
    int kend = CKLIM ? ((m0 + 128 < K) ? (m0 + 128) : K) : K;
    int NC = kend >> 6;

    int tid = threadIdx.x;
    int lane = tid & 31, wid = tid >> 5;
    int wm = wid & 3, wn = wid >> 2;
    uint32_t sb = smem_u32(smem);

    float acc[2][NT8][4];
#pragma unroll
    for (int i = 0; i < 2; i++)
#pragma unroll
        for (int j = 0; j < NT8; j++)
#pragma unroll
            for (int q = 0; q < 4; q++) acc[i][j][q] = 0.f;

    int crow = tid >> 3, cchk = tid & 7;          // cp.async thread mapping

    float4 ra[4][2];                              // CONVA register staging

    auto cp_stageB = [&](int ci) {
        int b = ci & 1;
        uint32_t base = sb + b * STAGE + 2 * SZAp;
        int k0 = ci * 64;
#pragma unroll
        for (int i = 0; i < NBI; i++) {
            int row = crow + i * 32;
            uint32_t off = sw128(row * 128 + cchk * 16);
            const u16* s = Bhi + (size_t)(n0 + row) * ldb + k0 + cchk * 8;
            cp16(base + off, s);
        }
#pragma unroll
        for (int i = 0; i < NBI; i++) {
            int row = crow + i * 32;
            uint32_t off = sw128(row * 128 + cchk * 16);
            const u16* s = Blo + (size_t)(n0 + row) * ldb + k0 + cchk * 8;
            cp16(base + SZBp + off, s);
        }
    };
    auto cp_stageA = [&](int ci) {
        int b = ci & 1;
        uint32_t base = sb + b * STAGE;
        int k0 = ci * 64;
#pragma unroll
        for (int i = 0; i < 4; i++) {
            int row = crow + i * 32;
            uint32_t off = sw128(row * 128 + cchk * 16);
            cp16(base + off, Ahi + (size_t)(m0 + row) * lda + k0 + cchk * 8);
        }
#pragma unroll
        for (int i = 0; i < 4; i++) {
            int row = crow + i * 32;
            uint32_t off = sw128(row * 128 + cchk * 16);
            cp16(base + SZAp + off, Alo + (size_t)(m0 + row) * lda + k0 + cchk * 8);
        }
    };
    auto loadA_regs = [&](int ci) {
        int k0 = ci * 64;
#pragma unroll
        for (int i = 0; i < 4; i++) {
            int idx = tid + i * 256;
            int row = idx >> 3, g = idx & 7;
            const float* s = Af + (size_t)(m0 + row) * lda + k0 + g * 8;
            ra[i][0] = *(const float4*)s;
            ra[i][1] = *(const float4*)(s + 4);
        }
    };
    auto storeA = [&](int ci) {
        int b = ci & 1;
        char* bufp = smem + b * STAGE;
#pragma unroll
        for (int i = 0; i < 4; i++) {
            int idx = tid + i * 256;
            int row = idx >> 3, g = idx & 7;
            uint4 hi, lo;
            conv8(ra[i][0], ra[i][1], hi, lo);
            uint32_t off = sw128(row * 128 + g * 16);
            *(uint4*)(bufp + off) = hi;
            *(uint4*)(bufp + SZAp + off) = lo;
        }
    };
    auto mma_chunk = [&](int b) {
        uint32_t bA = sb + b * STAGE;
        uint32_t bB = bA + 2 * SZAp;
        int g = lane >> 3;
#pragma unroll
        for (int ks = 0; ks < 4; ks++) {
            int kb = ks * 32;
            uint32_t ahi[2][4], alo[2][4];
#pragma unroll
            for (int mt = 0; mt < 2; mt++) {
                int row = wm * 32 + mt * 16 + (g & 1) * 8 + (lane & 7);
                uint32_t off = sw128(row * 128 + kb + (g >> 1) * 16);
                ldsm4(ahi[mt], bA + off);
                ldsm4(alo[mt], bA + SZAp + off);
            }
#pragma unroll
            for (int nt2 = 0; nt2 < NT8 / 2; nt2++) {
                int row = wn * WN + nt2 * 16 + (g >> 1) * 8 + (lane & 7);
                uint32_t off = sw128(row * 128 + kb + (g & 1) * 16);
                uint32_t bhi[4], blo[4];
                ldsm4(bhi, bB + off);
                ldsm4(blo, bB + SZBp + off);
#pragma unroll
                for (int mt = 0; mt < 2; mt++) {
#pragma unroll
                    for (int j = 0; j < 2; j++) {
                        float* c = acc[mt][nt2 * 2 + j];
                        mma16816(c, ahi[mt], bhi[2 * j], bhi[2 * j + 1]);
                        mma16816(c, ahi[mt], blo[2 * j], blo[2 * j + 1]);
                        mma16816(c, alo[mt], bhi[2 * j], bhi[2 * j + 1]);
                    }
                }
            }
        }
    };

    // ---- prologue ----
    if (CONVA) {
        loadA_regs(0);
        cp_stageB(0);
        cp_commit();
        storeA(0);
    } else {
        cp_stageA(0);
        cp_stageB(0);
        cp_commit();
    }
    // ---- main loop ----
    for (int ci = 0; ci < NC; ci++) {
        cp_wait<0>();
        __syncthreads();
        bool nxt = (ci + 1) < NC;
        if (nxt) {
            if (CONVA) {
                cp_stageB(ci + 1);
                cp_commit();
                loadA_regs(ci + 1);
            } else {
                cp_stageA(ci + 1);
                cp_stageB(ci + 1);
                cp_commit();
            }
        }
        mma_chunk(ci & 1);
        if (CONVA && nxt) storeA(ci + 1);
    }

    // ---- epilogue ----
#pragma unroll
    for (int mt = 0; mt < 2; mt++) {
#pragma unroll
        for (int nt = 0; nt < NT8; nt++) {
#pragma unroll
            for (int half = 0; half < 2; half++) {
                int m = m0 + wm * 32 + mt * 16 + (lane >> 2) + half * 8;
                int n = n0 + wn * WN + nt * 8 + (lane & 3) * 2;
                float v0 = acc[mt][nt][2 * half + 0] * scale;
                float v1 = acc[mt][nt][2 * half + 1] * scale;
                if (bias) {
                    float2 b2 = *(const float2*)(bias + n);
                    v0 += b2.x; v1 += b2.y;
                }
                if (EPI == 1) {
                    v0 = 0.5f * v0 * (1.0f + erff(v0 * 0.70710678118654752f));
                    v1 = 0.5f * v1 * (1.0f + erff(v1 * 0.70710678118654752f));
                }
                if (EPI == 2) {
                    float2 r2 = *(const float2*)(Res + (size_t)m * ldr + n);
                    v0 += r2.x; v1 += r2.y;
                }
                if (OSPLIT) {
                    *(uint32_t*)(Chi + (size_t)m * ldc + n) = hp2(v0, v1);
                    *(uint32_t*)(Clo + (size_t)m * ldc + n) = lp2(v0, v1);
                } else {
                    *(float2*)(C + (size_t)m * ldc + n) = make_float2(v0, v1);
                }
            }
        }
    }
}

// ---------------- split fp32 -> bf16 hi/lo planes -------------------------------
__global__ void splitf_kernel(const float* __restrict__ src, u16* __restrict__ hi,
                              u16* __restrict__ lo, int n4) {
    int i = blockIdx.x * blockDim.x + threadIdx.x;
    if (i >= n4) return;
    float4 v = ((const float4*)src)[i];
    uint2 hh = make_uint2(hp2(v.x, v.y), hp2(v.z, v.w));
    uint2 ll = make_uint2(lp2(v.x, v.y), lp2(v.z, v.w));
    ((uint2*)hi)[i] = hh;
    ((uint2*)lo)[i] = ll;
}

// ---------------- V transpose (bf16 planes): vt[h][d][t] = v[t][h*64+d] ----------
__global__ void vtrans_kernel(const u16* __restrict__ qhi, const u16* __restrict__ qlo,
                              u16* __restrict__ vthi, u16* __restrict__ vtlo) {
    __shared__ uint32_t ts[32][33];
    int h = blockIdx.z;
    int t0 = blockIdx.x * 32, d0 = blockIdx.y * 32;
    int tx = threadIdx.x, ty = threadIdx.y;
#pragma unroll
    for (int i = 0; i < 4; i++) {
        int t = t0 + ty + i * 8;
        size_t base = (size_t)t * (3 * CM) + 2 * CM + h * 64 + d0 + tx;
        ts[ty + i * 8][tx] = (uint32_t)qhi[base] | ((uint32_t)qlo[base] << 16);
    }
    __syncthreads();
#pragma unroll
    for (int i = 0; i < 4; i++) {
        int d = d0 + ty + i * 8;
        uint32_t v = ts[tx][ty + i * 8];
        size_t o = ((size_t)h * 64 + d) * TS + t0 + tx;
        vthi[o] = (u16)(v & 0xffff);
        vtlo[o] = (u16)(v >> 16);
    }
}

// ---------------- LayerNorm -> bf16 hi/lo planes --------------------------------
__global__ void ln_kernel(const float* __restrict__ x, const float* __restrict__ gw,
                          const float* __restrict__ bw, u16* __restrict__ ohi,
                          u16* __restrict__ olo) {
    int row = blockIdx.x;
    int tid = threadIdx.x;
    float4 v = ((const float4*)(x + (size_t)row * CM))[tid];
    float s  = v.x + v.y + v.z + v.w;
    float sq = v.x * v.x + v.y * v.y + v.z * v.z + v.w * v.w;
    __shared__ float rs[8], rq[8];
    __shared__ float s_mu, s_ri;
#pragma unroll
    for (int o = 16; o; o >>= 1) {
        s  += __shfl_xor_sync(0xffffffffu, s, o);
        sq += __shfl_xor_sync(0xffffffffu, sq, o);
    }
    if ((tid & 31) == 0) { rs[tid >> 5] = s; rq[tid >> 5] = sq; }
    __syncthreads();
    if (tid == 0) {
        float ts2 = 0.f, tq = 0.f;
#pragma unroll
        for (int i = 0; i < 8; i++) { ts2 += rs[i]; tq += rq[i]; }
        float mu  = ts2 * (1.0f / CM);
        float var = tq * (1.0f / CM) - mu * mu;
        s_mu = mu;
        s_ri = rsqrtf(var + 1e-5f);
    }
    __syncthreads();
    float mu = s_mu, ri = s_ri;
    float4 g4 = ((const float4*)gw)[tid];
    float4 b4 = ((const float4*)bw)[tid];
    float4 o4;
    o4.x = (v.x - mu) * ri * g4.x + b4.x;
    o4.y = (v.y - mu) * ri * g4.y + b4.y;
    o4.z = (v.z - mu) * ri * g4.z + b4.z;
    o4.w = (v.w - mu) * ri * g4.w + b4.w;
    uint2 hh = make_uint2(hp2(o4.x, o4.y), hp2(o4.z, o4.w));
    uint2 ll = make_uint2(lp2(o4.x, o4.y), lp2(o4.z, o4.w));
    ((uint2*)(ohi + (size_t)row * CM))[tid] = hh;
    ((uint2*)(olo + (size_t)row * CM))[tid] = ll;
}

// ---------------- Row softmax, causal, read-clipped ------------------------------
__global__ void softmax_kernel(float* __restrict__ attn) {
    int q = blockIdx.x, h = blockIdx.y;
    float* row = attn + ((size_t)h * TS + q) * (size_t)TS;
    int n = q + 1;
    int tcnt = (n + 1023) >> 10;   // 1024-col tiles that contain valid data
    int tid = threadIdx.x;
    float4 v[4];
    float lmax = -3.0e38f;
#pragma unroll
    for (int t = 0; t < 4; t++) {
        if (t < tcnt) {
            int j4 = tid + t * 256;
            v[t] = ((const float4*)row)[j4];
            int j = j4 * 4;
            if (j + 0 < n) lmax = fmaxf(lmax, v[t].x);
            if (j + 1 < n) lmax = fmaxf(lmax, v[t].y);
            if (j + 2 < n) lmax = fmaxf(lmax, v[t].z);
            if (j + 3 < n) lmax = fmaxf(lmax, v[t].w);
        }
    }
    __shared__ float red[8];
    __shared__ float bmax, bsum;
#pragma unroll
    for (int o = 16; o; o >>= 1) lmax = fmaxf(lmax, __shfl_xor_sync(0xffffffffu, lmax, o));
    if ((tid & 31) == 0) red[tid >> 5] = lmax;
    __syncthreads();
    if (tid == 0) {
        float m = red[0];
#pragma unroll
        for (int i = 1; i < 8; i++) m = fmaxf(m, red[i]);
        bmax = m;
    }
    __syncthreads();
    float m = bmax;
    float lsum = 0.f;
#pragma unroll
    for (int t = 0; t < 4; t++) {
        if (t < tcnt) {
            int j = (tid + t * 256) * 4;
            v[t].x = (j + 0 < n) ? __expf(v[t].x - m) : 0.0f;
            v[t].y = (j + 1 < n) ? __expf(v[t].y - m) : 0.0f;
            v[t].z = (j + 2 < n) ? __expf(v[t].z - m) : 0.0f;
            v[t].w = (j + 3 < n) ? __expf(v[t].w - m) : 0.0f;
            lsum += v[t].x + v[t].y + v[t].z + v[t].w;
        } else {
            v[t] = make_float4(0.f, 0.f, 0.f, 0.f);
        }
    }
#pragma unroll
    for (int o = 16; o; o >>= 1) lsum += __shfl_xor_sync(0xffffffffu, lsum, o);
    if ((tid & 31) == 0) red[tid >> 5] = lsum;
    __syncthreads();
    if (tid == 0) {
        float s = 0.f;
#pragma unroll
        for (int i = 0; i < 8; i++) s += red[i];
        bsum = s;
    }
    __syncthreads();
    float inv = 1.0f / bsum;
#pragma unroll
    for (int t = 0; t < 4; t++) {
        float4 o4 = make_float4(v[t].x * inv, v[t].y * inv, v[t].z * inv, v[t].w * inv);
        ((float4*)row)[tid + t * 256] = o4;
    }
}

// --------------------------------- launcher -------------------------------------
extern "C" void kernel_launch(void* const* d_in, const int* in_sizes, int n_in,
                              void* d_out, int out_size) {
    const float* x     = (const float*)d_in[0];
    const float* ln1_g = (const float*)d_in[1];
    const float* ln1_b = (const float*)d_in[2];
    const float* w_qkv = (const float*)d_in[3];
    const float* b_qkv = (const float*)d_in[4];
    const float* w_out = (const float*)d_in[5];
    const float* b_out = (const float*)d_in[6];
    const float* ln2_g = (const float*)d_in[7];
    const float* ln2_b = (const float*)d_in[8];
    const float* w1    = (const float*)d_in[9];
    const float* b1    = (const float*)d_in[10];
    const float* w2    = (const float*)d_in[11];
    const float* b2    = (const float*)d_in[12];

    float* out = (float*)d_out;
    size_t attn_elems = (size_t)NH * TS * TS;
    float* attn = out + ((size_t)out_size - attn_elems);

    u16 *ghh, *ghl, *qh, *ql, *vth, *vtl, *cxh, *cxl, *f1h, *f1l;
    u16 *wqh, *wql, *woh, *wol, *w1h, *w1l, *w2h, *w2l;
    float* gx1;
    cudaGetSymbolAddress((void**)&ghh, g_h_hi);
    cudaGetSymbolAddress((void**)&ghl, g_h_lo);
    cudaGetSymbolAddress((void**)&qh, g_qkv_hi);
    cudaGetSymbolAddress((void**)&ql, g_qkv_lo);
    cudaGetSymbolAddress((void**)&vth, g_vt_hi);
    cudaGetSymbolAddress((void**)&vtl, g_vt_lo);
    cudaGetSymbolAddress((void**)&cxh, g_ctx_hi);
    cudaGetSymbolAddress((void**)&cxl, g_ctx_lo);
    cudaGetSymbolAddress((void**)&f1h, g_ff1_hi);
    cudaGetSymbolAddress((void**)&f1l, g_ff1_lo);
    cudaGetSymbolAddress((void**)&wqh, g_wqkv_hi);
    cudaGetSymbolAddress((void**)&wql, g_wqkv_lo);
    cudaGetSymbolAddress((void**)&woh, g_wout_hi);
    cudaGetSymbolAddress((void**)&wol, g_wout_lo);
    cudaGetSymbolAddress((void**)&w1h, g_w1_hi);
    cudaGetSymbolAddress((void**)&w1l, g_w1_lo);
    cudaGetSymbolAddress((void**)&w2h, g_w2_hi);
    cudaGetSymbolAddress((void**)&w2l, g_w2_lo);
    cudaGetSymbolAddress((void**)&gx1, g_x1);

    const int SM128 = 2 * (2 * 128 * 128 + 2 * 128 * 128);  // 131072
    const int SM64  = 2 * (2 * 128 * 128 + 2 * 64 * 128);   //  98304
    cudaFuncSetAttribute((void*)tgemm<128, 0, false, false, false, true >, cudaFuncAttributeMaxDynamicSharedMemorySize, SM128);
    cudaFuncSetAttribute((void*)tgemm<128, 0, true,  false, false, false>, cudaFuncAttributeMaxDynamicSharedMemorySize, SM128);
    cudaFuncSetAttribute((void*)tgemm<64,  0, false, true,  true,  true >, cudaFuncAttributeMaxDynamicSharedMemorySize, SM64);
    cudaFuncSetAttribute((void*)tgemm<128, 2, false, false, false, false>, cudaFuncAttributeMaxDynamicSharedMemorySize, SM128);
    cudaFuncSetAttribute((void*)tgemm<128, 1, false, false, false, true >, cudaFuncAttributeMaxDynamicSharedMemorySize, SM128);

    // 0. weight splits
    splitf_kernel<<<(3 * CM * CM / 4 + 255) / 256, 256>>>(w_qkv, wqh, wql, 3 * CM * CM / 4);
    splitf_kernel<<<(CM * CM / 4 + 255) / 256, 256>>>(w_out, woh, wol, CM * CM / 4);
    splitf_kernel<<<(DFF * CM / 4 + 255) / 256, 256>>>(w1, w1h, w1l, DFF * CM / 4);
    splitf_kernel<<<(CM * DFF / 4 + 255) / 256, 256>>>(w2, w2h, w2l, CM * DFF / 4);
    // 1. LN1 -> planes
    ln_kernel<<<TS, 256>>>(x, ln1_g, ln1_b, ghh, ghl);
    // 2. QKV -> qkv planes
    tgemm<128, 0, false, false, false, true><<<dim3(24, 32, 1), 256, SM128>>>(
        ghh, ghl, nullptr, CM, 0, wqh, wql, CM, 0,
        nullptr, qh, ql, 3 * CM, 0, b_qkv, nullptr, 0, CM, 1.0f);
    // 3. V transpose (bf16 planes)
    vtrans_kernel<<<dim3(TS / 32, 2, NH), dim3(32, 8)>>>(qh, ql, vth, vtl);
    // 4. Scores: Q @ K^T / 8 -> attn fp32 (causal skip)
    tgemm<128, 0, true, false, false, false><<<dim3(32, 32, NH), 256, SM128>>>(
        qh, ql, nullptr, 3 * CM, 64, qh + CM, ql + CM, 3 * CM, 64,
        attn, nullptr, nullptr, TS, (long long)TS * TS, nullptr, nullptr, 0, 64, 0.125f);
    // 5. Softmax (causal zero-fill, clipped reads)
    softmax_kernel<<<dim3(TS, NH), 256>>>(attn);
    // 6. PV: attn(fp32, conv in-kernel) @ Vt^T -> ctx planes (causal K clamp)
    tgemm<64, 0, false, true, true, true><<<dim3(1, 32, NH), 256, SM64>>>(
        nullptr, nullptr, attn, TS, (long long)TS * TS, vth, vtl, TS, (long long)64 * TS,
        nullptr, cxh, cxl, CM, 64, nullptr, nullptr, 0, TS, 1.0f);
    // 7. Out projection + residual(x) -> x1 fp32
    tgemm<128, 2, false, false, false, false><<<dim3(8, 32, 1), 256, SM128>>>(
        cxh, cxl, nullptr, CM, 0, woh, wol, CM, 0,
        gx1, nullptr, nullptr, CM, 0, b_out, x, CM, CM, 1.0f);
    // 8. LN2 -> planes
    ln_kernel<<<TS, 256>>>(gx1, ln2_g, ln2_b, ghh, ghl);
    // 9. FF1 + GELU -> ff1 planes
    tgemm<128, 1, false, false, false, true><<<dim3(32, 32, 1), 256, SM128>>>(
        ghh, ghl, nullptr, CM, 0, w1h, w1l, CM, 0,
        nullptr, f1h, f1l, DFF, 0, b1, nullptr, 0, CM, 1.0f);
    // 10. FF2 + residual(x1) -> final x
    tgemm<128, 2, false, false, false, false><<<dim3(8, 32, 1), 256, SM128>>>(
        f1h, f1l, nullptr, DFF, 0, w2h, w2l, DFF, 0,
        out, nullptr, nullptr, CM, 0, b2, gx1, CM, DFF, 1.0f);
}